// round 3
// baseline (speedup 1.0000x reference)
#include <cuda_runtime.h>
#include <cuda_bf16.h>
#include <mma.h>

using namespace nvcuda;

// Problem constants
#define GB   2        // batch
#define GN   256      // num anchor blocks
#define GL   4        // layers
#define GS   4096     // seq len
#define GH   2048     // hidden
#define NH   16       // heads
#define DH   128      // head dim
#define BSQ  16       // block size (queries per anchor block)
#define NHD  2048     // NH*DH
#define MM   2048     // B*N*L rows of context GEMM
#define KNN  4096     // concat output cols (Wkc | Wvc)
#define SCALE 0.08838834764831845f  // 1/sqrt(128)

// Scratch: context GEMM output  C[m, 0:2048] = k_chs, C[m, 2048:4096] = v_chs
__device__ float g_C[(size_t)MM * KNN];

// Read anchor value regardless of whether the harness stored int32 or int64.
__device__ __forceinline__ bool anchor_is_i64(const void* anchor) {
    const long long* a64 = (const long long*)anchor;
    bool ok = true;
    #pragma unroll
    for (int i = 0; i < 4; i++) {
        long long t = a64[i];
        if (t < 0 || t >= GS) ok = false;
    }
    return ok;
}

__device__ __forceinline__ long long anchor_read(const void* anchor, int idx, bool is64) {
    if (is64) return ((const long long*)anchor)[idx];
    return (long long)((const int*)anchor)[idx];
}

// ---------------------------------------------------------------------------
// Kernel 1: gathered tf32 GEMM
//   A[m,k] = hidden_states[l, b, ctx(b,n), k]  with m = ((b*N+n)*L + l)
//   Bmat   = [W_kc | W_vc]  (2048 x 4096), row-major
//   C      = A @ Bmat   (2048 x 4096)
// Tile: BM=64, BN=128, BK=16; 8 warps, each computes 32x32 via 2x2 wmma tiles.
// ---------------------------------------------------------------------------
__global__ __launch_bounds__(256) void gemm_ctx_kernel(
    const float* __restrict__ hidden,
    const void* __restrict__ anchor,
    const float* __restrict__ Wkc,
    const float* __restrict__ Wvc)
{
    const int bx = blockIdx.x;   // output-col tile (128 wide): 0..31
    const int by = blockIdx.y;   // output-row tile (64 tall):  0..31
    const int tid = threadIdx.x;

    __shared__ float  As[64][24];     // stride 24 (mult of 8, 16B-aligned rows)
    __shared__ float  Bs[16][136];    // stride 136 (mult of 8)
    __shared__ size_t rowbase[64];

    if (tid < 64) {
        const bool is64 = anchor_is_i64(anchor);
        int m  = by * 64 + tid;
        int l  = m & 3;
        int bn = m >> 2;
        int b  = bn >> 8;
        int n  = bn & 255;
        long long a = anchor_read(anchor, b * GN + n, is64) - 1;
        if (a < 0) a = 0;
        if (a > GS - 1) a = GS - 1;   // defensive clamp: never OOB
        rowbase[tid] = (((size_t)l * GB + b) * GS + (size_t)a) * GH;
    }

    // A whole 128-wide col tile lives entirely in Wkc (bx<16) or Wvc.
    const float* Wbase = (bx < 16) ? (Wkc + bx * 128) : (Wvc + (bx - 16) * 128);

    wmma::fragment<wmma::accumulator, 16, 16, 8, float> acc[2][2];
    #pragma unroll
    for (int i = 0; i < 2; i++)
        #pragma unroll
        for (int j = 0; j < 2; j++)
            wmma::fill_fragment(acc[i][j], 0.0f);

    const int warp = tid >> 5;
    const int wm = warp & 1;      // 0..1 -> 32-row slice
    const int wn = warp >> 1;     // 0..3 -> 32-col slice

    __syncthreads();

    const int arow = tid >> 2;
    const int ac4  = (tid & 3) << 2;

    for (int k0 = 0; k0 < GH; k0 += 16) {
        // Load A tile: 64 rows x 16 cols, one float4 per thread (gathered rows)
        float4 av = *reinterpret_cast<const float4*>(hidden + rowbase[arow] + k0 + ac4);
        *reinterpret_cast<float4*>(&As[arow][ac4]) = av;

        // Load B tile: 16 rows x 128 cols, two float4 per thread
        #pragma unroll
        for (int r = 0; r < 2; r++) {
            int idx  = tid + r * 256;
            int brow = idx >> 5;            // 0..15
            int bc4  = (idx & 31) << 2;     // 0..124
            float4 bv = *reinterpret_cast<const float4*>(
                Wbase + (size_t)(k0 + brow) * NHD + bc4);
            *reinterpret_cast<float4*>(&Bs[brow][bc4]) = bv;
        }
        __syncthreads();

        #pragma unroll
        for (int ks = 0; ks < 16; ks += 8) {
            wmma::fragment<wmma::matrix_a, 16, 16, 8, wmma::precision::tf32, wmma::row_major> afrag[2];
            wmma::fragment<wmma::matrix_b, 16, 16, 8, wmma::precision::tf32, wmma::row_major> bfrag[2];
            #pragma unroll
            for (int i = 0; i < 2; i++) {
                wmma::load_matrix_sync(afrag[i], &As[wm * 32 + i * 16][ks], 24);
                #pragma unroll
                for (int t = 0; t < afrag[i].num_elements; t++)
                    afrag[i].x[t] = wmma::__float_to_tf32(afrag[i].x[t]);
            }
            #pragma unroll
            for (int j = 0; j < 2; j++) {
                wmma::load_matrix_sync(bfrag[j], &Bs[ks][wn * 32 + j * 16], 136);
                #pragma unroll
                for (int t = 0; t < bfrag[j].num_elements; t++)
                    bfrag[j].x[t] = wmma::__float_to_tf32(bfrag[j].x[t]);
            }
            #pragma unroll
            for (int i = 0; i < 2; i++)
                #pragma unroll
                for (int j = 0; j < 2; j++)
                    wmma::mma_sync(acc[i][j], afrag[i], bfrag[j], acc[i][j]);
        }
        __syncthreads();
    }

    #pragma unroll
    for (int i = 0; i < 2; i++)
        #pragma unroll
        for (int j = 0; j < 2; j++) {
            int row = by * 64 + wm * 32 + i * 16;
            int col = bx * 128 + wn * 32 + j * 16;
            wmma::store_matrix_sync(&g_C[(size_t)row * KNN + col], acc[i][j],
                                    KNN, wmma::mem_row_major);
        }
}

// ---------------------------------------------------------------------------
// Kernel 2: block-local attention.
// One block per (b, n, h). Keys/values = 4 context rows (from g_C) + 16 block
// rows (from k/v). 16 queries. All tiles in smem; warp per pair of queries.
// ---------------------------------------------------------------------------
__global__ __launch_bounds__(256) void attn_kernel(
    const float* __restrict__ q,
    const float* __restrict__ k,
    const float* __restrict__ v,
    const int* __restrict__ mask,          // bool stored as int32 by harness
    float* __restrict__ out)
{
    const int bid = blockIdx.x;        // ((b*N + n)*NH + h)
    const int h  = bid & 15;
    const int bn = bid >> 4;
    const int n  = bn & 255;
    const int b  = bn >> 8;

    __shared__ float Qs[16][128];
    __shared__ float Ks[20][128];
    __shared__ float Vs[20][128];

    const int tid = threadIdx.x;

    // Base of q/k/v rows for this (b, n, h): row r at qbase + r*2048
    const size_t qbase = ((size_t)(b * (GN * BSQ) + n * BSQ) * NH + h) * DH;

    // Q tile: 16 rows x 128 = 512 float4
    for (int idx = tid; idx < 512; idx += 256) {
        int r = idx >> 5, c = (idx & 31) << 2;
        *reinterpret_cast<float4*>(&Qs[r][c]) =
            *reinterpret_cast<const float4*>(&q[qbase + (size_t)r * (NH * DH) + c]);
    }

    // K/V tiles: 20 rows x 128 = 640 float4 each
    const size_t cbase = (size_t)((b * GN + n) * GL) * KNN + (size_t)h * DH;
    for (int idx = tid; idx < 640; idx += 256) {
        int r = idx >> 5, c = (idx & 31) << 2;
        float4 kv4, vv4;
        if (r < GL) {
            kv4 = *reinterpret_cast<const float4*>(&g_C[cbase + (size_t)r * KNN + c]);
            vv4 = *reinterpret_cast<const float4*>(&g_C[cbase + (size_t)r * KNN + NHD + c]);
        } else {
            size_t off = qbase + (size_t)(r - GL) * (NH * DH) + c;
            kv4 = *reinterpret_cast<const float4*>(&k[off]);
            vv4 = *reinterpret_cast<const float4*>(&v[off]);
        }
        *reinterpret_cast<float4*>(&Ks[r][c]) = kv4;
        *reinterpret_cast<float4*>(&Vs[r][c]) = vv4;
    }
    __syncthreads();

    const int lane = tid & 31;
    const int warp = tid >> 5;
    const float keep = (mask[b * GN + n] != 0) ? 1.0f : 0.0f;

    for (int qi = warp; qi < 16; qi += 8) {
        float s[20];
        #pragma unroll
        for (int j = 0; j < 20; j++) {
            float acc = 0.0f;
            #pragma unroll
            for (int t = 0; t < 4; t++)
                acc += Qs[qi][lane + 32 * t] * Ks[j][lane + 32 * t];
            #pragma unroll
            for (int o = 16; o; o >>= 1)
                acc += __shfl_xor_sync(0xffffffff, acc, o);
            s[j] = acc * SCALE;
        }
        float mx = s[0];
        #pragma unroll
        for (int j = 1; j < 20; j++) mx = fmaxf(mx, s[j]);
        float sum = 0.0f;
        #pragma unroll
        for (int j = 0; j < 20; j++) { s[j] = __expf(s[j] - mx); sum += s[j]; }
        const float inv = keep / sum;

        float o0 = 0.f, o1 = 0.f, o2 = 0.f, o3 = 0.f;
        #pragma unroll
        for (int j = 0; j < 20; j++) {
            float p = s[j];
            o0 += p * Vs[j][lane];
            o1 += p * Vs[j][lane + 32];
            o2 += p * Vs[j][lane + 64];
            o3 += p * Vs[j][lane + 96];
        }
        const size_t obase =
            ((size_t)(b * (GN * BSQ) + n * BSQ + qi)) * NHD + (size_t)h * DH;
        out[obase + lane]       = o0 * inv;
        out[obase + lane + 32]  = o1 * inv;
        out[obase + lane + 64]  = o2 * inv;
        out[obase + lane + 96]  = o3 * inv;
    }
}

// ---------------------------------------------------------------------------
// kernel_launch
// Inputs (metadata order): hidden_states f32, anchor_positions (i32/i64),
// block_keep_mask (int32), q f32, k f32, v f32, W_kc f32, W_vc f32.
// Output: f32 (B, N*BS, NH*DH) = 16,777,216 elems.
// ---------------------------------------------------------------------------
extern "C" void kernel_launch(void* const* d_in, const int* in_sizes, int n_in,
                              void* d_out, int out_size)
{
    const float* hidden = (const float*)d_in[0];
    const void*  anchor = d_in[1];
    const int*   mask   = (const int*)d_in[2];
    const float* q      = (const float*)d_in[3];
    const float* k      = (const float*)d_in[4];
    const float* v      = (const float*)d_in[5];
    const float* Wkc    = (const float*)d_in[6];
    const float* Wvc    = (const float*)d_in[7];

    dim3 ggrid(KNN / 128, MM / 64);     // (32, 32)
    gemm_ctx_kernel<<<ggrid, 256>>>(hidden, anchor, Wkc, Wvc);

    attn_kernel<<<GB * GN * NH, 256>>>(q, k, v, mask, (float*)d_out);
}